// round 1
// baseline (speedup 1.0000x reference)
#include <cuda_runtime.h>
#include <math.h>

// out[i,j] = | prod_k cos((x[i,k] - y[j,k]) / 2) |
// cos((a-b)/2) = cos(a/2)cos(b/2) + sin(a/2)sin(b/2)
// -> precompute (cos, sin) of half-angles, then pure-FMA product-accumulate.

#define CS_CAP (1 << 20)
__device__ float2 g_xcs[CS_CAP];  // k-major: [k*n + i] = (cos(x/2), sin(x/2))
__device__ float2 g_ycs[CS_CAP];

typedef unsigned long long u64;

__device__ __forceinline__ u64 fma2(u64 a, u64 b, u64 c) {
    u64 d;
    asm("fma.rn.f32x2 %0, %1, %2, %3;" : "=l"(d) : "l"(a), "l"(b), "l"(c));
    return d;
}
__device__ __forceinline__ u64 mul2(u64 a, u64 b) {
    u64 d;
    asm("mul.rn.f32x2 %0, %1, %2;" : "=l"(d) : "l"(a), "l"(b));
    return d;
}
__device__ __forceinline__ u64 dup2(float x) {
    u64 d;
    asm("mov.b64 %0, {%1, %2};" : "=l"(d) : "f"(x), "f"(x));
    return d;
}

// Write (cos(v/2), sin(v/2)) in k-major layout for coalesced tile fills.
__global__ void qk_precompute(const float* __restrict__ v, int n, int d, int which) {
    float2* o = which ? g_ycs : g_xcs;
    int idx = blockIdx.x * blockDim.x + threadIdx.x;
    if (idx >= n * d) return;
    int i = idx % n;
    int k = idx / n;
    float s, c;
    sincosf(0.5f * v[i * d + k], &s, &c);
    o[k * n + i] = make_float2(c, s);
}

// 128x128 tile per CTA, 256 threads, 8x8 outputs/thread (as 8x4 f32x2 pairs).
__global__ __launch_bounds__(256, 2)
void qk_main(float* __restrict__ out, int n, int m) {
    __shared__ u64   s_xc[16][128];   // duplicated (c,c) pairs  -> 16KB
    __shared__ u64   s_xs[16][128];   // duplicated (s,s) pairs  -> 16KB
    __shared__ float s_yc[16][128];   // scalar cos              -> 8KB
    __shared__ float s_ys[16][128];   // scalar sin              -> 8KB

    const int tid = threadIdx.x;
    const int i0 = blockIdx.y * 128;
    const int j0 = blockIdx.x * 128;

    // Tile fill: global reads coalesced (k-major source), smem stores conflict-free.
    #pragma unroll
    for (int e = tid; e < 16 * 128; e += 256) {
        int k = e >> 7, r = e & 127;
        float2 xcs = g_xcs[k * n + i0 + r];
        s_xc[k][r] = dup2(xcs.x);
        s_xs[k][r] = dup2(xcs.y);
        float2 ycs = g_ycs[k * m + j0 + r];
        s_yc[k][r] = ycs.x;
        s_ys[k][r] = ycs.y;
    }
    __syncthreads();

    const int tx = tid & 15;   // j dimension (16 threads)
    const int ty = tid >> 4;   // i dimension (16 threads)

    u64 acc[8][4];
    const u64 ONE2 = 0x3f8000003f800000ULL;  // (1.0f, 1.0f)
    #pragma unroll
    for (int ii = 0; ii < 8; ii++)
        #pragma unroll
        for (int jj = 0; jj < 4; jj++) acc[ii][jj] = ONE2;

    #pragma unroll 4
    for (int k = 0; k < 16; k++) {
        u64 yc[4], ys[4];
        #pragma unroll
        for (int jj = 0; jj < 4; jj++) {
            // j-pair (2*tx, 2*tx+1) + 32*jj : 8B-aligned, conflict-free across tx
            yc[jj] = *(const u64*)&s_yc[k][2 * tx + 32 * jj];
            ys[jj] = *(const u64*)&s_ys[k][2 * tx + 32 * jj];
        }
        #pragma unroll
        for (int ii = 0; ii < 8; ii++) {
            u64 xc = s_xc[k][ty + 16 * ii];   // broadcast within warp
            u64 xs = s_xs[k][ty + 16 * ii];
            #pragma unroll
            for (int jj = 0; jj < 4; jj++) {
                u64 t = fma2(xc, yc[jj], mul2(xs, ys[jj]));
                acc[ii][jj] = mul2(acc[ii][jj], t);
            }
        }
    }

    // abs via bitmask, 8B vectorized stores (coalesced per half-warp)
    #pragma unroll
    for (int ii = 0; ii < 8; ii++) {
        int i = i0 + ty + 16 * ii;
        float* orow = out + (size_t)i * m + j0;
        #pragma unroll
        for (int jj = 0; jj < 4; jj++) {
            u64 a = acc[ii][jj] & 0x7fffffff7fffffffULL;
            *(u64*)&orow[2 * tx + 32 * jj] = a;
        }
    }
}

// Generic fallback for unexpected shapes.
__global__ void qk_naive(const float* __restrict__ x, const float* __restrict__ y,
                         float* __restrict__ out, int n, int m, int d) {
    int j = blockIdx.x * blockDim.x + threadIdx.x;
    int i = blockIdx.y;
    if (i >= n || j >= m) return;
    float p = 1.0f;
    for (int k = 0; k < d; k++)
        p *= cosf(0.5f * (x[i * d + k] - y[j * d + k]));
    out[(size_t)i * m + j] = fabsf(p);
}

extern "C" void kernel_launch(void* const* d_in, const int* in_sizes, int n_in,
                              void* d_out, int out_size) {
    const float* x = (const float*)d_in[0];
    const float* y = (const float*)d_in[1];
    float* out = (float*)d_out;

    long long sx = in_sizes[0], sy = in_sizes[1], so = out_size;
    int d = (int)llround(sqrt((double)sx * (double)sy / (double)so));
    if (d <= 0) d = 16;
    int n = (int)(sx / d);
    int m = (int)(sy / d);

    if (d == 16 && n % 128 == 0 && m % 128 == 0 &&
        (long long)n * d <= CS_CAP && (long long)m * d <= CS_CAP) {
        int tx = n * d, ty = m * d;
        qk_precompute<<<(tx + 255) / 256, 256>>>(x, n, d, 0);
        qk_precompute<<<(ty + 255) / 256, 256>>>(y, m, d, 1);
        dim3 grid(m / 128, n / 128);
        qk_main<<<grid, 256>>>(out, n, m);
    } else {
        qk_naive<<<dim3((m + 255) / 256, n), 256>>>(x, y, out, n, m, d);
    }
}

// round 3
// speedup vs baseline: 1.2691x; 1.2691x over previous
#include <cuda_runtime.h>
#include <math.h>

// out[i,j] = | prod_k cos((x[i,k] - y[j,k]) / 2) |
// cos((a-b)/2) = cos(a/2)cos(b/2) + sin(a/2)sin(b/2)
// Fully fused: per-CTA __sincosf prologue -> pure f32x2-FMA product mainloop.

typedef unsigned long long u64;

__device__ __forceinline__ u64 fma2(u64 a, u64 b, u64 c) {
    u64 d;
    asm("fma.rn.f32x2 %0, %1, %2, %3;" : "=l"(d) : "l"(a), "l"(b), "l"(c));
    return d;
}
__device__ __forceinline__ u64 mul2(u64 a, u64 b) {
    u64 d;
    asm("mul.rn.f32x2 %0, %1, %2;" : "=l"(d) : "l"(a), "l"(b));
    return d;
}
__device__ __forceinline__ u64 dup2(float x) {
    u64 d;
    asm("mov.b64 %0, {%1, %2};" : "=l"(d) : "f"(x), "f"(x));
    return d;
}

// 128x128 tile per CTA, 256 threads, 8x8 outputs/thread (as 8x4 f32x2 pairs).
// Smem: 16KB x (float2 interleaved) + 16KB y (split cos/sin) = 32KB, occ 2.
__global__ __launch_bounds__(256, 2)
void qk_fused(const float* __restrict__ x, const float* __restrict__ y,
              float* __restrict__ out, int n, int m) {
    __shared__ float2 s_x[16][128];   // [k][r^k]       = (cos, sin) of x/2
    __shared__ float  s_yc[16][128];  // [k][j ^ (2k)]  = cos(y/2)
    __shared__ float  s_ys[16][128];  // [k][j ^ (2k)]  = sin(y/2)

    const int tid = threadIdx.x;
    const int i0 = blockIdx.y * 128;
    const int j0 = blockIdx.x * 128;

    // Prologue: coalesced gmem reads (k fast), swizzled conflict-free(ish) stores.
    #pragma unroll
    for (int c = 0; c < 8; c++) {
        int e = tid + 256 * c;
        int r = e >> 4, k = e & 15;
        float sx, cx;
        __sincosf(0.5f * x[(i0 + r) * 16 + k], &sx, &cx);
        s_x[k][r ^ k] = make_float2(cx, sx);
        float sy, cy;
        __sincosf(0.5f * y[(j0 + r) * 16 + k], &sy, &cy);
        int rs = r ^ ((k & 15) << 1);
        s_yc[k][rs] = cy;
        s_ys[k][rs] = sy;
    }
    __syncthreads();

    const int tx = tid & 15;   // j dimension (16 threads)
    const int ty = tid >> 4;   // i dimension (16 threads)

    u64 acc[8][4];
    const u64 ONE2 = 0x3f8000003f800000ULL;  // (1.0f, 1.0f)
    #pragma unroll
    for (int ii = 0; ii < 8; ii++)
        #pragma unroll
        for (int jj = 0; jj < 4; jj++) acc[ii][jj] = ONE2;

    #pragma unroll 4
    for (int k = 0; k < 16; k++) {
        const int jy = ((tx ^ k) << 1);  // swizzled base for this k's y row
        u64 yc[4], ys[4];
        #pragma unroll
        for (int jj = 0; jj < 4; jj++) {
            yc[jj] = *(const u64*)&s_yc[k][jy + 32 * jj];
            ys[jj] = *(const u64*)&s_ys[k][jy + 32 * jj];
        }
        #pragma unroll
        for (int ii = 0; ii < 8; ii++) {
            float2 xcs = s_x[k][(ty + 16 * ii) ^ k];  // broadcast (2 addrs/warp)
            u64 xc = dup2(xcs.x);
            u64 xs = dup2(xcs.y);
            #pragma unroll
            for (int jj = 0; jj < 4; jj++) {
                u64 t = fma2(xc, yc[jj], mul2(xs, ys[jj]));
                acc[ii][jj] = mul2(acc[ii][jj], t);
            }
        }
    }

    // abs via bitmask, 8B vectorized stores (coalesced per half-warp)
    #pragma unroll
    for (int ii = 0; ii < 8; ii++) {
        int i = i0 + ty + 16 * ii;
        float* orow = out + (size_t)i * m + j0;
        #pragma unroll
        for (int jj = 0; jj < 4; jj++) {
            u64 a = acc[ii][jj] & 0x7fffffff7fffffffULL;
            *(u64*)&orow[2 * tx + 32 * jj] = a;
        }
    }
}

// Generic fallback for unexpected shapes.
__global__ void qk_naive(const float* __restrict__ x, const float* __restrict__ y,
                         float* __restrict__ out, int n, int m, int d) {
    int j = blockIdx.x * blockDim.x + threadIdx.x;
    int i = blockIdx.y;
    if (i >= n || j >= m) return;
    float p = 1.0f;
    for (int k = 0; k < d; k++)
        p *= cosf(0.5f * (x[i * d + k] - y[j * d + k]));
    out[(size_t)i * m + j] = fabsf(p);
}

extern "C" void kernel_launch(void* const* d_in, const int* in_sizes, int n_in,
                              void* d_out, int out_size) {
    const float* x = (const float*)d_in[0];
    const float* y = (const float*)d_in[1];
    float* out = (float*)d_out;

    long long sx = in_sizes[0], sy = in_sizes[1], so = out_size;
    int d = (int)llround(sqrt((double)sx * (double)sy / (double)so));
    if (d <= 0) d = 16;
    int n = (int)(sx / d);
    int m = (int)(sy / d);

    if (d == 16 && n % 128 == 0 && m % 128 == 0) {
        dim3 grid(m / 128, n / 128);
        qk_fused<<<grid, 256>>>(x, y, out, n, m);
    } else {
        qk_naive<<<dim3((m + 255) / 256, n), 256>>>(x, y, out, n, m, d);
    }
}